// round 1
// baseline (speedup 1.0000x reference)
#include <cuda_runtime.h>

#define BB 2
#define NN 16384
#define SS 4096
#define KSAMP 32
#define CF 64
#define D1 64
#define D2 64
#define D3 128
#define CPB 8

// scratch (allocation-free rule: __device__ globals)
__device__ __align__(16) float4 g_pts[BB * NN];          // x,y,z,|p|^2
__device__ __align__(16) float  g_F1[BB * NN * D1];      // feat part of layer1 (+b1)
__device__ __align__(16) int    g_idx[BB * SS * KSAMP];

// out layout: [new_xyz BB*SS*3][new_features BB*D3*SS][samp_idx BB*SS]
#define OUT_FEAT_BASE (BB * SS * 3)
#define OUT_SAMP_BASE (BB * SS * 3 + BB * D3 * SS)

// ---------------------------------------------------------------------------
__global__ void prep_pts(const float* __restrict__ xyz, float* __restrict__ out) {
    int i = blockIdx.x * blockDim.x + threadIdx.x;
    if (i >= BB * NN) return;
    int b = i / NN, n = i % NN;
    float x = xyz[i * 3 + 0], y = xyz[i * 3 + 1], z = xyz[i * 3 + 2];
    float nn = x * x + y * y + z * z;
    g_pts[i] = make_float4(x, y, z, nn);
    if (n < SS) {
        int o = (b * SS + n) * 3;
        out[o + 0] = x; out[o + 1] = y; out[o + 2] = z;
        out[OUT_SAMP_BASE + b * SS + n] = (float)n;
    }
}

// ---------------------------------------------------------------------------
// F1[b][n][co] = b1[co] + sum_c feats[b][c][n] * W1[3+c][co]
__global__ void prep_F1(const float* __restrict__ feats, const float* __restrict__ W1,
                        const float* __restrict__ b1) {
    __shared__ float Ws[CF * D1];
    __shared__ float ft[CF][64 + 1];
    int t = threadIdx.x;
    int tile = blockIdx.x;                 // BB*NN/64 tiles
    int b = tile / (NN / 64);
    int n0 = (tile % (NN / 64)) * 64;

    for (int e = t; e < CF * D1; e += 256) Ws[e] = W1[(3 + e / D1) * D1 + (e % D1)];
    for (int e = t; e < CF * 64; e += 256) {
        int c = e >> 6, nl = e & 63;
        ft[c][nl] = feats[(b * CF + c) * NN + n0 + nl];
    }
    __syncthreads();

    int nl = t & 63;
    int cog = t >> 6;                      // 4 groups of 16 outputs
    float acc[16];
#pragma unroll
    for (int j = 0; j < 16; j++) acc[j] = b1[cog * 16 + j];
    for (int c = 0; c < CF; c++) {
        float f = ft[c][nl];
        const float4* w4 = (const float4*)&Ws[c * D1 + cog * 16];
#pragma unroll
        for (int q = 0; q < 4; q++) {
            float4 w = w4[q];
            acc[q * 4 + 0] = fmaf(f, w.x, acc[q * 4 + 0]);
            acc[q * 4 + 1] = fmaf(f, w.y, acc[q * 4 + 1]);
            acc[q * 4 + 2] = fmaf(f, w.z, acc[q * 4 + 2]);
            acc[q * 4 + 3] = fmaf(f, w.w, acc[q * 4 + 3]);
        }
    }
    float4* dst = (float4*)&g_F1[(size_t)(b * NN + n0 + nl) * D1 + cog * 16];
#pragma unroll
    for (int q = 0; q < 4; q++)
        dst[q] = make_float4(acc[q * 4 + 0], acc[q * 4 + 1], acc[q * 4 + 2], acc[q * 4 + 3]);
}

// ---------------------------------------------------------------------------
// ball query: 1 warp per centroid, first KSAMP hits in index order, fill=first
__global__ void ballq() {
    const float R2 = (float)(0.4 * 0.4);   // matches jnp's f32 cast of double 0.16
    int lane = threadIdx.x & 31;
    int cid = blockIdx.x * 8 + (threadIdx.x >> 5);
    int b = cid / SS, s = cid % SS;
    const float4* pts = &g_pts[b * NN];
    float4 c = pts[s];
    int cnt = 0, first = 0;
    for (int base = 0; base < NN; base += 32) {
        float4 p = pts[base + lane];
        float dot = c.x * p.x + c.y * p.y + c.z * p.z;
        float d2 = (c.w + p.w) - 2.0f * dot;
        bool hit = d2 < R2;
        unsigned m = __ballot_sync(0xffffffffu, hit);
        if (m) {
            if (cnt == 0) first = __shfl_sync(0xffffffffu, base + lane, __ffs(m) - 1);
            int pos = cnt + __popc(m & ((1u << lane) - 1u));
            if (hit && pos < KSAMP) g_idx[cid * KSAMP + pos] = base + lane;
            cnt += __popc(m);
            if (cnt >= KSAMP) break;
        }
    }
    if (lane >= cnt) g_idx[cid * KSAMP + lane] = first;
}

// ---------------------------------------------------------------------------
// fused layer1-gather + layer2 + layer3 + max, CPB centroids per 256-thr block
#define H1ST 65
#define H2ST 68
#define SM_FLOATS (D1*D2 + D2*D3 + D2 + D3 + 3*D1 + KSAMP*H1ST + KSAMP*H2ST + 8*D3 + 4*KSAMP)
#define SM_BYTES (SM_FLOATS * 4)

__global__ void __launch_bounds__(256) mlp_kernel(
    const float* __restrict__ W1, const float* __restrict__ W2,
    const float* __restrict__ b2, const float* __restrict__ W3,
    const float* __restrict__ b3, float* __restrict__ out) {
    extern __shared__ float sm[];
    float* W2s = sm;                       // [c][d] 64x64
    float* W3s = W2s + D1 * D2;            // [c][d] 64x128
    float* b2s = W3s + D2 * D3;
    float* b3s = b2s + D2;
    float* w1x = b3s + D3;
    float* w1y = w1x + D1;
    float* w1z = w1y + D1;
    float* h1s = w1z + D1;                 // [32][65]
    float* h2s = h1s + KSAMP * H1ST;       // [32][68]
    float* red = h2s + KSAMP * H2ST;       // [8][128]
    float* rxs = red + 8 * D3;
    float* rys = rxs + KSAMP;
    float* rzs = rys + KSAMP;
    int*   ids = (int*)(rzs + KSAMP);

    int t = threadIdx.x;
    for (int e = t; e < D1 * D2; e += 256) W2s[e] = W2[e];
    for (int e = t; e < D2 * D3; e += 256) W3s[e] = W3[e];
    if (t < D2) b2s[t] = b2[t];
    if (t < D3) b3s[t] = b3[t];
    if (t < D1) { w1x[t] = W1[t]; w1y[t] = W1[D1 + t]; w1z[t] = W1[2 * D1 + t]; }
    __syncthreads();

    for (int ci = 0; ci < CPB; ci++) {
        int cid = blockIdx.x * CPB + ci;
        int b = cid / SS, s = cid % SS;

        // phase 0: relative xyz + idx to shared
        if (t < KSAMP) {
            int id = g_idx[cid * KSAMP + t];
            float4 p = g_pts[b * NN + id];
            float4 cc = g_pts[b * NN + s];
            rxs[t] = p.x - cc.x; rys[t] = p.y - cc.y; rzs[t] = p.z - cc.z;
            ids[t] = id;
        }
        __syncthreads();

        // phase 1: h1[k][c] = relu(F1[id_k][c] + rel . W1xyz[c])
        {
            int c = t & 63;
            int kg = t >> 6;               // 4 groups of 8 samples
#pragma unroll
            for (int i = 0; i < 8; i++) {
                int k = kg * 8 + i;
                float v = g_F1[(size_t)(b * NN + ids[k]) * D1 + c];
                v = fmaf(rxs[k], w1x[c], v);
                v = fmaf(rys[k], w1y[c], v);
                v = fmaf(rzs[k], w1z[c], v);
                h1s[k * H1ST + c] = fmaxf(v, 0.0f);
            }
        }
        __syncthreads();

        // phase 2: h2 = relu(h1 @ W2 + b2). thread: 2 k x 4 d
        {
            int kp = t >> 4;               // 0..15 -> k {kp, kp+16}
            int dq = t & 15;               // d = dq*4
            float a0 = 0, a1 = 0, a2 = 0, a3 = 0;
            float c0 = 0, c1 = 0, c2 = 0, c3 = 0;
#pragma unroll 4
            for (int c = 0; c < D1; c++) {
                float4 w = *(const float4*)&W2s[c * D2 + dq * 4];
                float ha = h1s[kp * H1ST + c];
                float hb = h1s[(kp + 16) * H1ST + c];
                a0 = fmaf(ha, w.x, a0); a1 = fmaf(ha, w.y, a1);
                a2 = fmaf(ha, w.z, a2); a3 = fmaf(ha, w.w, a3);
                c0 = fmaf(hb, w.x, c0); c1 = fmaf(hb, w.y, c1);
                c2 = fmaf(hb, w.z, c2); c3 = fmaf(hb, w.w, c3);
            }
            float4 bb = *(const float4*)&b2s[dq * 4];
            float* ra = &h2s[kp * H2ST + dq * 4];
            float* rb = &h2s[(kp + 16) * H2ST + dq * 4];
            ra[0] = fmaxf(a0 + bb.x, 0.f); ra[1] = fmaxf(a1 + bb.y, 0.f);
            ra[2] = fmaxf(a2 + bb.z, 0.f); ra[3] = fmaxf(a3 + bb.w, 0.f);
            rb[0] = fmaxf(c0 + bb.x, 0.f); rb[1] = fmaxf(c1 + bb.y, 0.f);
            rb[2] = fmaxf(c2 + bb.z, 0.f); rb[3] = fmaxf(c3 + bb.w, 0.f);
        }
        __syncthreads();

        // phase 3: out[d] = max_k relu(h2[k] @ W3[:,d] + b3[d]). thread: 4 k x 4 d
        {
            int dq = t & 31;               // d = dq*4
            int kg = t >> 5;               // 8 groups of 4 samples
            float acc[4][4];
#pragma unroll
            for (int j = 0; j < 4; j++)
#pragma unroll
                for (int i = 0; i < 4; i++) acc[j][i] = 0.f;
#pragma unroll 2
            for (int c = 0; c < D2; c++) {
                float4 w = *(const float4*)&W3s[c * D3 + dq * 4];
#pragma unroll
                for (int j = 0; j < 4; j++) {
                    float h = h2s[(kg * 4 + j) * H2ST + c];
                    acc[j][0] = fmaf(h, w.x, acc[j][0]);
                    acc[j][1] = fmaf(h, w.y, acc[j][1]);
                    acc[j][2] = fmaf(h, w.z, acc[j][2]);
                    acc[j][3] = fmaf(h, w.w, acc[j][3]);
                }
            }
            float4 bv = *(const float4*)&b3s[dq * 4];
            float m0 = 0.f, m1 = 0.f, m2 = 0.f, m3 = 0.f; // relu >= 0
#pragma unroll
            for (int j = 0; j < 4; j++) {
                m0 = fmaxf(m0, acc[j][0] + bv.x);
                m1 = fmaxf(m1, acc[j][1] + bv.y);
                m2 = fmaxf(m2, acc[j][2] + bv.z);
                m3 = fmaxf(m3, acc[j][3] + bv.w);
            }
            *(float4*)&red[kg * D3 + dq * 4] = make_float4(m0, m1, m2, m3);
        }
        __syncthreads();
        if (t < D3) {
            float m = red[t];
#pragma unroll
            for (int g = 1; g < 8; g++) m = fmaxf(m, red[g * D3 + t]);
            out[OUT_FEAT_BASE + (size_t)b * D3 * SS + (size_t)t * SS + s] = m;
        }
        __syncthreads();
    }
}

// ---------------------------------------------------------------------------
extern "C" void kernel_launch(void* const* d_in, const int* in_sizes, int n_in,
                              void* d_out, int out_size) {
    const float* xyz   = (const float*)d_in[0];
    const float* feats = (const float*)d_in[1];
    const float* W1    = (const float*)d_in[2];
    const float* b1    = (const float*)d_in[3];
    const float* W2    = (const float*)d_in[4];
    const float* b2    = (const float*)d_in[5];
    const float* W3    = (const float*)d_in[6];
    const float* b3    = (const float*)d_in[7];
    float* out = (float*)d_out;
    (void)in_sizes; (void)n_in; (void)out_size;

    cudaFuncSetAttribute(mlp_kernel, cudaFuncAttributeMaxDynamicSharedMemorySize, SM_BYTES);

    prep_pts<<<(BB * NN + 255) / 256, 256>>>(xyz, out);
    prep_F1<<<BB * NN / 64, 256>>>(feats, W1, b1);
    ballq<<<BB * SS / 8, 256>>>();
    mlp_kernel<<<BB * SS / CPB, 256, SM_BYTES>>>(W1, W2, b2, W3, b3, out);
}

// round 2
// speedup vs baseline: 1.0957x; 1.0957x over previous
#include <cuda_runtime.h>

#define BB 2
#define NN 16384
#define SS 4096
#define KSAMP 32
#define CF 64
#define D1 64
#define D2 64
#define D3 128
#define CPB 8
#define H1ST 36
#define H2ST 36

typedef unsigned long long u64;

// scratch (__device__ globals per allocation rule)
__device__ __align__(16) float4 g_pts[BB * NN];     // x,y,z,|p|^2
__device__ __align__(16) float  g_px[BB * NN];
__device__ __align__(16) float  g_py[BB * NN];
__device__ __align__(16) float  g_pz[BB * NN];
__device__ __align__(16) float  g_F1[BB * NN * D1]; // feat part of layer1 (+b1)
__device__ __align__(16) int    g_idx[BB * SS * KSAMP];

#define OUT_FEAT_BASE (BB * SS * 3)
#define OUT_SAMP_BASE (BB * SS * 3 + BB * D3 * SS)

// ---- packed f32x2 helpers -------------------------------------------------
__device__ __forceinline__ u64 fma2(u64 a, u64 b, u64 c) {
    u64 d;
    asm("fma.rn.f32x2 %0, %1, %2, %3;" : "=l"(d) : "l"(a), "l"(b), "l"(c));
    return d;
}
__device__ __forceinline__ u64 pack2(float lo, float hi) {
    u64 d;
    asm("mov.b64 %0, {%1, %2};" : "=l"(d) : "f"(lo), "f"(hi));
    return d;
}
__device__ __forceinline__ void unpack2(u64 v, float& lo, float& hi) {
    asm("mov.b64 {%0, %1}, %2;" : "=f"(lo), "=f"(hi) : "l"(v));
}

// ---------------------------------------------------------------------------
__global__ void prep_pts(const float* __restrict__ xyz, float* __restrict__ out) {
    int i = blockIdx.x * blockDim.x + threadIdx.x;
    if (i >= BB * NN) return;
    int b = i / NN, n = i % NN;
    float x = xyz[i * 3 + 0], y = xyz[i * 3 + 1], z = xyz[i * 3 + 2];
    float nn = x * x + y * y + z * z;
    g_pts[i] = make_float4(x, y, z, nn);
    g_px[i] = x; g_py[i] = y; g_pz[i] = z;
    if (n < SS) {
        int o = (b * SS + n) * 3;
        out[o + 0] = x; out[o + 1] = y; out[o + 2] = z;
        out[OUT_SAMP_BASE + b * SS + n] = (float)n;
    }
}

// ---------------------------------------------------------------------------
// F1[b][n][co] = b1[co] + sum_c feats[b][c][n] * W1[3+c][co]
__global__ void prep_F1(const float* __restrict__ feats, const float* __restrict__ W1,
                        const float* __restrict__ b1) {
    __shared__ float Ws[CF * D1];
    __shared__ float ft[CF][64 + 1];
    int t = threadIdx.x;
    int tile = blockIdx.x;
    int b = tile / (NN / 64);
    int n0 = (tile % (NN / 64)) * 64;

    for (int e = t; e < CF * D1; e += 256) Ws[e] = W1[(3 + e / D1) * D1 + (e % D1)];
    for (int e = t; e < CF * 64; e += 256) {
        int c = e >> 6, nl = e & 63;
        ft[c][nl] = feats[(b * CF + c) * NN + n0 + nl];
    }
    __syncthreads();

    int nl = t & 63;
    int cog = t >> 6;
    float acc[16];
#pragma unroll
    for (int j = 0; j < 16; j++) acc[j] = b1[cog * 16 + j];
    for (int c = 0; c < CF; c++) {
        float f = ft[c][nl];
        const float4* w4 = (const float4*)&Ws[c * D1 + cog * 16];
#pragma unroll
        for (int q = 0; q < 4; q++) {
            float4 w = w4[q];
            acc[q * 4 + 0] = fmaf(f, w.x, acc[q * 4 + 0]);
            acc[q * 4 + 1] = fmaf(f, w.y, acc[q * 4 + 1]);
            acc[q * 4 + 2] = fmaf(f, w.z, acc[q * 4 + 2]);
            acc[q * 4 + 3] = fmaf(f, w.w, acc[q * 4 + 3]);
        }
    }
    float4* dst = (float4*)&g_F1[(size_t)(b * NN + n0 + nl) * D1 + cog * 16];
#pragma unroll
    for (int q = 0; q < 4; q++)
        dst[q] = make_float4(acc[q * 4 + 0], acc[q * 4 + 1], acc[q * 4 + 2], acc[q * 4 + 3]);
}

// ---------------------------------------------------------------------------
// ball query: block of 8 warps shares 256-point tiles via smem; SoA xyz;
// |p|^2 recomputed with the identical expression as prep (bit-identical).
__global__ void __launch_bounds__(256) ballq() {
    const float R2 = (float)(0.4 * 0.4);
    __shared__ float tx[256], ty[256], tz[256];
    int t = threadIdx.x;
    int lane = t & 31;
    int w = t >> 5;
    int cid = blockIdx.x * 8 + w;
    int b = cid / SS, s = cid % SS;
    const float* px = g_px + b * NN;
    const float* py = g_py + b * NN;
    const float* pz = g_pz + b * NN;

    float cx = px[s], cy = py[s], cz = pz[s];
    float cw = cx * cx + cy * cy + cz * cz;

    int cnt = 0, first = 0;
    for (int base = 0; base < NN; base += 256) {
        __syncthreads();
        tx[t] = px[base + t]; ty[t] = py[base + t]; tz[t] = pz[base + t];
        __syncthreads();
        if (cnt < KSAMP) {
#pragma unroll
            for (int j = 0; j < 8; j++) {
                int li = j * 32 + lane;
                float qx = tx[li], qy = ty[li], qz = tz[li];
                float dot = cx * qx + cy * qy + cz * qz;
                float qw = qx * qx + qy * qy + qz * qz;
                float d2 = (cw + qw) - 2.0f * dot;
                bool hit = d2 < R2;
                unsigned m = __ballot_sync(0xffffffffu, hit);
                if (m) {
                    if (cnt == 0) first = base + j * 32 + (__ffs(m) - 1);
                    int pos = cnt + __popc(m & ((1u << lane) - 1u));
                    if (hit && pos < KSAMP) g_idx[cid * KSAMP + pos] = base + j * 32 + lane;
                    cnt += __popc(m);
                    if (cnt >= KSAMP) break;
                }
            }
        }
        if (__syncthreads_and(cnt >= KSAMP)) break;
    }
    if (lane >= cnt) g_idx[cid * KSAMP + lane] = first;
}

// ---------------------------------------------------------------------------
// fused MLP: transposed [c][k] activations + packed f32x2 FMAs
#define SM_FLOATS (D1*D2 + D2*D3 + D2 + D3 + 3*D1 + CF*H1ST + D2*H2ST + 3*KSAMP + KSAMP + D3*CPB)
#define SM_BYTES (SM_FLOATS * 4)

__global__ void __launch_bounds__(256) mlp_kernel(
    const float* __restrict__ W1, const float* __restrict__ W2,
    const float* __restrict__ b2, const float* __restrict__ W3,
    const float* __restrict__ b3, float* __restrict__ out) {
    extern __shared__ float sm[];
    float* W2s = sm;                        // [c][d] 64x64
    float* W3s = W2s + D1 * D2;             // [c][d] 64x128
    float* b2s = W3s + D2 * D3;
    float* b3s = b2s + D2;
    float* w1x = b3s + D3;
    float* w1y = w1x + D1;
    float* w1z = w1y + D1;
    float* h1T = w1z + D1;                  // [c=64][k pad 36]
    float* h2T = h1T + CF * H1ST;           // [c=64][k pad 36]
    float* rxs = h2T + D2 * H2ST;
    float* rys = rxs + KSAMP;
    float* rzs = rys + KSAMP;
    int*   ids = (int*)(rzs + KSAMP);
    float* outb = (float*)(ids + KSAMP);    // [d=128][ci=8]

    int t = threadIdx.x;
    for (int e = t; e < D1 * D2; e += 256) W2s[e] = W2[e];
    for (int e = t; e < D2 * D3; e += 256) W3s[e] = W3[e];
    if (t < D2) b2s[t] = b2[t];
    if (t < D3) b3s[t] = b3[t];
    if (t < D1) { w1x[t] = W1[t]; w1y[t] = W1[D1 + t]; w1z[t] = W1[2 * D1 + t]; }
    __syncthreads();

    // per-thread constants
    const int c1 = t & 63, kg1 = t >> 6;               // phase1: 1 c x 8 k
    const float vx = w1x[c1], vy = w1y[c1], vz = w1z[c1];
    const int kg2 = t & 7, dg2 = t >> 3;               // phase2: 4 k x 2 d
    const float b2v0 = b2s[dg2 * 2], b2v1 = b2s[dg2 * 2 + 1];
    const int kg3 = t & 3, dg3 = t >> 2;               // phase3: 8 k x 2 d
    const float b3v0 = b3s[dg3 * 2], b3v1 = b3s[dg3 * 2 + 1];

    const int cid0 = blockIdx.x * CPB;
    const int b = cid0 / SS;
    const int s0 = cid0 % SS;
    const float* F1b = g_F1 + (size_t)b * NN * D1;
    const float4* ptsb = g_pts + b * NN;

    for (int ci = 0; ci < CPB; ci++) {
        int s = s0 + ci;
        // phase 0: rel xyz + idx
        if (t < KSAMP) {
            int id = g_idx[(size_t)(cid0 + ci) * KSAMP + t];
            float4 p = ptsb[id];
            float4 cc = ptsb[s];
            rxs[t] = p.x - cc.x; rys[t] = p.y - cc.y; rzs[t] = p.z - cc.z;
            ids[t] = id;
        }
        __syncthreads();

        // phase 1: h1T[c][k] = relu(F1[id_k][c] + rel_k . w1[c])
        {
            float vals[8];
#pragma unroll
            for (int i = 0; i < 8; i++) {
                int k = kg1 * 8 + i;
                float v = F1b[(size_t)ids[k] * D1 + c1];
                v = fmaf(rxs[k], vx, v);
                v = fmaf(rys[k], vy, v);
                v = fmaf(rzs[k], vz, v);
                vals[i] = fmaxf(v, 0.0f);
            }
            float* dst = &h1T[c1 * H1ST + kg1 * 8];
            *(float4*)dst       = make_float4(vals[0], vals[1], vals[2], vals[3]);
            *(float4*)(dst + 4) = make_float4(vals[4], vals[5], vals[6], vals[7]);
        }
        __syncthreads();

        // phase 2: h2 = relu(h1 @ W2 + b2); acc packed over k pairs
        {
            u64 a00 = pack2(b2v0, b2v0), a01 = pack2(b2v1, b2v1);
            u64 a10 = a00, a11 = a01;
#pragma unroll 4
            for (int c = 0; c < D1; c++) {
                ulonglong2 hp = *(const ulonglong2*)&h1T[c * H1ST + kg2 * 4];
                float2 w = *(const float2*)&W2s[c * D2 + dg2 * 2];
                u64 wa = pack2(w.x, w.x), wb = pack2(w.y, w.y);
                a00 = fma2(hp.x, wa, a00); a01 = fma2(hp.x, wb, a01);
                a10 = fma2(hp.y, wa, a10); a11 = fma2(hp.y, wb, a11);
            }
            float lo, hi;
            float* r0 = &h2T[(dg2 * 2) * H2ST + kg2 * 4];
            float* r1 = &h2T[(dg2 * 2 + 1) * H2ST + kg2 * 4];
            unpack2(a00, lo, hi); *(float2*)r0       = make_float2(fmaxf(lo, 0.f), fmaxf(hi, 0.f));
            unpack2(a10, lo, hi); *(float2*)(r0 + 2) = make_float2(fmaxf(lo, 0.f), fmaxf(hi, 0.f));
            unpack2(a01, lo, hi); *(float2*)r1       = make_float2(fmaxf(lo, 0.f), fmaxf(hi, 0.f));
            unpack2(a11, lo, hi); *(float2*)(r1 + 2) = make_float2(fmaxf(lo, 0.f), fmaxf(hi, 0.f));
        }
        __syncthreads();

        // phase 3: out[d] = max_k relu(h2[k] @ W3[:,d] + b3[d])
        {
            u64 acc[4][2];
#pragma unroll
            for (int i = 0; i < 4; i++) {
                acc[i][0] = pack2(b3v0, b3v0);
                acc[i][1] = pack2(b3v1, b3v1);
            }
#pragma unroll 4
            for (int c = 0; c < D2; c++) {
                ulonglong2 hA = *(const ulonglong2*)&h2T[c * H2ST + kg3 * 8];
                ulonglong2 hB = *(const ulonglong2*)&h2T[c * H2ST + kg3 * 8 + 4];
                float2 w = *(const float2*)&W3s[c * D3 + dg3 * 2];
                u64 wa = pack2(w.x, w.x), wb = pack2(w.y, w.y);
                acc[0][0] = fma2(hA.x, wa, acc[0][0]); acc[0][1] = fma2(hA.x, wb, acc[0][1]);
                acc[1][0] = fma2(hA.y, wa, acc[1][0]); acc[1][1] = fma2(hA.y, wb, acc[1][1]);
                acc[2][0] = fma2(hB.x, wa, acc[2][0]); acc[2][1] = fma2(hB.x, wb, acc[2][1]);
                acc[3][0] = fma2(hB.y, wa, acc[3][0]); acc[3][1] = fma2(hB.y, wb, acc[3][1]);
            }
            float m0 = 0.f, m1 = 0.f, lo, hi;
#pragma unroll
            for (int i = 0; i < 4; i++) {
                unpack2(acc[i][0], lo, hi); m0 = fmaxf(m0, fmaxf(lo, hi));
                unpack2(acc[i][1], lo, hi); m1 = fmaxf(m1, fmaxf(lo, hi));
            }
            m0 = fmaxf(m0, __shfl_xor_sync(0xffffffffu, m0, 1));
            m0 = fmaxf(m0, __shfl_xor_sync(0xffffffffu, m0, 2));
            m1 = fmaxf(m1, __shfl_xor_sync(0xffffffffu, m1, 1));
            m1 = fmaxf(m1, __shfl_xor_sync(0xffffffffu, m1, 2));
            if (kg3 == 0) {
                outb[(dg3 * 2) * CPB + ci] = m0;
                outb[(dg3 * 2 + 1) * CPB + ci] = m1;
            }
        }
        __syncthreads();
    }

    // flush: [d][ci] -> out[b][d][s0+ci], coalesced float4
    {
        int d = t >> 1, so = (t & 1) * 4;
        float4 v = *(const float4*)&outb[d * CPB + so];
        *(float4*)&out[OUT_FEAT_BASE + (size_t)b * D3 * SS + (size_t)d * SS + s0 + so] = v;
    }
}

// ---------------------------------------------------------------------------
extern "C" void kernel_launch(void* const* d_in, const int* in_sizes, int n_in,
                              void* d_out, int out_size) {
    const float* xyz   = (const float*)d_in[0];
    const float* feats = (const float*)d_in[1];
    const float* W1    = (const float*)d_in[2];
    const float* b1    = (const float*)d_in[3];
    const float* W2    = (const float*)d_in[4];
    const float* b2    = (const float*)d_in[5];
    const float* W3    = (const float*)d_in[6];
    const float* b3    = (const float*)d_in[7];
    float* out = (float*)d_out;
    (void)in_sizes; (void)n_in; (void)out_size;

    cudaFuncSetAttribute(mlp_kernel, cudaFuncAttributeMaxDynamicSharedMemorySize, SM_BYTES);

    prep_pts<<<(BB * NN + 255) / 256, 256>>>(xyz, out);
    prep_F1<<<BB * NN / 64, 256>>>(feats, W1, b1);
    ballq<<<BB * SS / 8, 256>>>();
    mlp_kernel<<<BB * SS / CPB, 256, SM_BYTES>>>(W1, W2, b2, W3, b3, out);
}